// round 1
// baseline (speedup 1.0000x reference)
#include <cuda_runtime.h>
#include <math.h>
#include <stdint.h>

// ---------------- problem constants ----------------
#define BATCH 2
#define SEQ   2048
#define T_TOK 4096          // BATCH*SEQ
#define HIDN  2560
#define NH    32
#define NKV   8
#define HD    128
#define QDIM  4096          // NH*HD
#define KVDIM 1024          // NKV*HD

// ---------------- scratch (static device allocations; no cudaMalloc) ----------------
__device__ float g_hid_r[(size_t)T_TOK * HIDN];
__device__ float g_Wq_r[(size_t)HIDN * QDIM];
__device__ float g_Wk_r[(size_t)HIDN * KVDIM];
__device__ float g_Wv_r[(size_t)HIDN * KVDIM];
__device__ float g_Wo_r[(size_t)QDIM * HIDN];
__device__ float g_q[(size_t)T_TOK * QDIM];
__device__ float g_k[(size_t)T_TOK * KVDIM];
__device__ float g_v[(size_t)T_TOK * KVDIM];
__device__ float g_ao[(size_t)T_TOK * QDIM];
__device__ float g_cos[(size_t)T_TOK * 64];
__device__ float g_sin[(size_t)T_TOK * 64];

// ---------------- helpers ----------------
__device__ __forceinline__ float tf32r(float x) {
    unsigned u;
    asm("cvt.rna.tf32.f32 %0, %1;" : "=r"(u) : "f"(x));
    return __uint_as_float(u);
}

__device__ __forceinline__ void cp16(void* smem_dst, const void* gsrc) {
    unsigned d = (unsigned)__cvta_generic_to_shared(smem_dst);
    asm volatile("cp.async.cg.shared.global [%0], [%1], 16;\n" :: "r"(d), "l"(gsrc));
}

// ---------------- tf32 round pass ----------------
__global__ void round4_kernel(const float4* __restrict__ in, float4* __restrict__ out, int n4) {
    int i = blockIdx.x * blockDim.x + threadIdx.x;
    int stride = gridDim.x * blockDim.x;
    for (; i < n4; i += stride) {
        float4 v = in[i];
        v.x = tf32r(v.x); v.y = tf32r(v.y); v.z = tf32r(v.z); v.w = tf32r(v.w);
        out[i] = v;
    }
}

// ---------------- RoPE cos/sin table (double precision) ----------------
__global__ void rope_table_kernel(const int* __restrict__ p32) {
    int idx = blockIdx.x * blockDim.x + threadIdx.x;
    if (idx >= T_TOK * 64) return;
    int t = idx >> 6;
    int i = idx & 63;
    // Detect int64 vs int32 position_ids layout (values are small non-negative).
    // int32: p32 = [0,1,2,...]; int64 LE: p32 = [0,0,1,0,2,0,...]
    bool is64 = (p32[1] == 0 && p32[2] == 1);
    int pos = is64 ? p32[2 * t] : p32[t];
    double ang = (double)pos * exp(-(double)i * (log(1000000.0) / 64.0));
    g_cos[idx] = (float)cos(ang);
    g_sin[idx] = (float)sin(ang);
}

// ---------------- tf32 mma GEMM: C[M,N] = A[M,K] @ B[K,N] (all row-major fp32) ----------------
#define GBM 128
#define GBN 128
#define GBK 32
#define AST 36     // A smem row stride (pad: conflict-free frag loads)
#define BST 136    // B smem row stride

__device__ __forceinline__ void gemm_load_tiles(
    const float* __restrict__ A, const float* __restrict__ B,
    int N, int K, int mBase, int nBase, int kt,
    float* As, float* Bs, int tid)
{
    const float* Ag = A + (size_t)mBase * K + (size_t)kt * GBK;
#pragma unroll
    for (int i = 0; i < 4; i++) {
        int e = tid + i * 256;
        int r = e >> 3, ks = (e & 7) << 2;
        cp16(&As[r * AST + ks], Ag + (size_t)r * K + ks);
    }
    const float* Bg = B + (size_t)(kt * GBK) * N + nBase;
#pragma unroll
    for (int i = 0; i < 4; i++) {
        int e = tid + i * 256;
        int r = e >> 5, ns = (e & 31) << 2;
        cp16(&Bs[r * BST + ns], Bg + (size_t)r * N + ns);
    }
    asm volatile("cp.async.commit_group;\n");
}

__global__ void __launch_bounds__(256) gemm_tf32_kernel(
    const float* __restrict__ A, const float* __restrict__ B, float* __restrict__ C,
    int M, int N, int K)
{
    extern __shared__ float smem[];
    float* As = smem;                       // 2 stages * 128*36
    float* Bs = smem + 2 * GBM * AST;       // 2 stages * 32*136

    const int tid = threadIdx.x;
    const int warp = tid >> 5, lane = tid & 31;
    const int wm = warp >> 2, wn = warp & 3;     // 2 x 4 warp grid
    const int g = lane >> 2, tq = lane & 3;      // quad layout
    const int mBase = blockIdx.y * GBM;
    const int nBase = blockIdx.x * GBN;

    float c[4][4][4];
#pragma unroll
    for (int a = 0; a < 4; a++)
#pragma unroll
        for (int bq = 0; bq < 4; bq++)
#pragma unroll
            for (int e = 0; e < 4; e++) c[a][bq][e] = 0.f;

    const int KT = K / GBK;
    gemm_load_tiles(A, B, N, K, mBase, nBase, 0, As, Bs, tid);

    for (int kt = 0; kt < KT; kt++) {
        float* as = As + (kt & 1) * GBM * AST;
        float* bs = Bs + (kt & 1) * GBK * BST;
        if (kt + 1 < KT) {
            gemm_load_tiles(A, B, N, K, mBase, nBase, kt + 1,
                            As + ((kt + 1) & 1) * GBM * AST,
                            Bs + ((kt + 1) & 1) * GBK * BST, tid);
            asm volatile("cp.async.wait_group 1;\n");
        } else {
            asm volatile("cp.async.wait_group 0;\n");
        }
        __syncthreads();

#pragma unroll
        for (int ks = 0; ks < 4; ks++) {
            const int k0 = ks * 8;
            unsigned af[4][4];
            unsigned bf[4][2];
#pragma unroll
            for (int mt = 0; mt < 4; mt++) {
                int r0 = wm * 64 + mt * 16;
                af[mt][0] = __float_as_uint(as[(r0 + g)     * AST + k0 + tq]);
                af[mt][1] = __float_as_uint(as[(r0 + g + 8) * AST + k0 + tq]);
                af[mt][2] = __float_as_uint(as[(r0 + g)     * AST + k0 + tq + 4]);
                af[mt][3] = __float_as_uint(as[(r0 + g + 8) * AST + k0 + tq + 4]);
            }
#pragma unroll
            for (int nt = 0; nt < 4; nt++) {
                int c0 = wn * 32 + nt * 8;
                bf[nt][0] = __float_as_uint(bs[(k0 + tq)     * BST + c0 + g]);
                bf[nt][1] = __float_as_uint(bs[(k0 + tq + 4) * BST + c0 + g]);
            }
#pragma unroll
            for (int mt = 0; mt < 4; mt++)
#pragma unroll
                for (int nt = 0; nt < 4; nt++) {
                    asm volatile(
                        "mma.sync.aligned.m16n8k8.row.col.f32.tf32.tf32.f32 "
                        "{%0,%1,%2,%3},{%4,%5,%6,%7},{%8,%9},{%0,%1,%2,%3};"
                        : "+f"(c[mt][nt][0]), "+f"(c[mt][nt][1]),
                          "+f"(c[mt][nt][2]), "+f"(c[mt][nt][3])
                        : "r"(af[mt][0]), "r"(af[mt][1]), "r"(af[mt][2]), "r"(af[mt][3]),
                          "r"(bf[nt][0]), "r"(bf[nt][1]));
                }
        }
        __syncthreads();
    }

    // epilogue
#pragma unroll
    for (int mt = 0; mt < 4; mt++) {
        int r0 = mBase + wm * 64 + mt * 16;
#pragma unroll
        for (int nt = 0; nt < 4; nt++) {
            int c0 = nBase + wn * 32 + nt * 8 + tq * 2;
            *(float2*)&C[(size_t)(r0 + g)     * N + c0] = make_float2(c[mt][nt][0], c[mt][nt][1]);
            *(float2*)&C[(size_t)(r0 + g + 8) * N + c0] = make_float2(c[mt][nt][2], c[mt][nt][3]);
        }
    }
}

// ---------------- fused RMSNorm + RoPE (in-place on g_q / g_k) ----------------
__global__ void __launch_bounds__(128) norm_rope_kernel(
    const float* __restrict__ qw, const float* __restrict__ kw)
{
    int rid = blockIdx.x;
    int tid = threadIdx.x;
    float* buf;
    const float* w;
    int t;
    if (rid < T_TOK * NH) {
        t = rid / NH;
        int h = rid % NH;
        buf = g_q + (size_t)t * QDIM + (size_t)h * HD;
        w = qw;
    } else {
        rid -= T_TOK * NH;
        t = rid / NKV;
        int h = rid % NKV;
        buf = g_k + (size_t)t * KVDIM + (size_t)h * HD;
        w = kw;
    }
    float x = buf[tid];
    float s = x * x;
#pragma unroll
    for (int o = 16; o > 0; o >>= 1) s += __shfl_xor_sync(0xffffffffu, s, o);
    __shared__ float ws[4];
    __shared__ float sh[128];
    if ((tid & 31) == 0) ws[tid >> 5] = s;
    __syncthreads();
    s = ws[0] + ws[1] + ws[2] + ws[3];
    float y = x * rsqrtf(s * (1.0f / 128.0f) + 1e-6f) * w[tid];
    sh[tid] = y;
    __syncthreads();
    float c = g_cos[(size_t)t * 64 + (tid & 63)];
    float sn = g_sin[(size_t)t * 64 + (tid & 63)];
    float rot = (tid < 64) ? -sh[tid + 64] : sh[tid - 64];
    buf[tid] = y * c + rot * sn;
}

// ---------------- fp32 flash attention (64x64 tiles, online softmax) ----------------
#define QST 132
#define PST 68
#define ATTN_SMEM ((3 * 64 * QST + 64 * PST + 3 * 64) * 4)

__global__ void __launch_bounds__(256) attn_kernel() {
    extern __shared__ float sm[];
    float* Qs = sm;                       // [64][132]
    float* Ks = Qs + 64 * QST;            // [64][132]
    float* Vs = Ks + 64 * QST;            // [64][132]
    float* Ps = Vs + 64 * QST;            // [64][68]
    float* m_s  = Ps + 64 * PST;          // [64]
    float* l_s  = m_s + 64;               // [64]
    float* al_s = l_s + 64;               // [64]

    const int qt = blockIdx.x, h = blockIdx.y, b = blockIdx.z;
    const int kvh = h >> 2;               // G = NH/NKV = 4
    const int tid = threadIdx.x;
    const int warp = tid >> 5, lane = tid & 31;
    const int wr = warp >> 1, wk = warp & 1;   // 4 row-groups x 2 key/d halves
    const int lr = lane >> 3, lc = lane & 7;
    const int tBase = b * SEQ + qt * 64;
    const int d0 = wk * 64 + lc * 8;
    const float scale = 0.08838834764831845f;  // 128^-0.5

    // load Q tile
#pragma unroll
    for (int i = 0; i < 8; i++) {
        int e = tid + (i << 8);
        int r = e >> 5, ds = (e & 31) << 2;
        *(float4*)&Qs[r * QST + ds] =
            *(const float4*)&g_q[(size_t)(tBase + r) * QDIM + (size_t)h * HD + ds];
    }
    if (tid < 64) { m_s[tid] = -1e30f; l_s[tid] = 0.f; }

    float acc[4][8];
#pragma unroll
    for (int i = 0; i < 4; i++)
#pragma unroll
        for (int j = 0; j < 8; j++) acc[i][j] = 0.f;

    for (int kt = 0; kt <= qt; kt++) {
        int kBase = b * SEQ + kt * 64;
#pragma unroll
        for (int i = 0; i < 8; i++) {
            int e = tid + (i << 8);
            int r = e >> 5, ds = (e & 31) << 2;
            *(float4*)&Ks[r * QST + ds] =
                *(const float4*)&g_k[(size_t)(kBase + r) * KVDIM + (size_t)kvh * HD + ds];
            *(float4*)&Vs[r * QST + ds] =
                *(const float4*)&g_v[(size_t)(kBase + r) * KVDIM + (size_t)kvh * HD + ds];
        }
        __syncthreads();

        // --- QK^T : warp covers 16 rows x 32 keys; lane 4x4 micro-tile ---
        float sc[4][4];
#pragma unroll
        for (int i = 0; i < 4; i++)
#pragma unroll
            for (int j = 0; j < 4; j++) sc[i][j] = 0.f;

#pragma unroll 8
        for (int d = 0; d < HD; d += 4) {
            float4 qv[4], kv[4];
#pragma unroll
            for (int i = 0; i < 4; i++)
                qv[i] = *(const float4*)&Qs[(wr * 16 + i * 4 + lr) * QST + d];
#pragma unroll
            for (int j = 0; j < 4; j++)
                kv[j] = *(const float4*)&Ks[(wk * 32 + j * 8 + lc) * QST + d];
#pragma unroll
            for (int i = 0; i < 4; i++)
#pragma unroll
                for (int j = 0; j < 4; j++)
                    sc[i][j] += qv[i].x * kv[j].x + qv[i].y * kv[j].y +
                                qv[i].z * kv[j].z + qv[i].w * kv[j].w;
        }

        // scale + causal mask -> Ps
#pragma unroll
        for (int i = 0; i < 4; i++) {
            int rl = wr * 16 + i * 4 + lr;
#pragma unroll
            for (int j = 0; j < 4; j++) {
                int kl = wk * 32 + j * 8 + lc;
                float v = sc[i][j] * scale;
                if (kt * 64 + kl > qt * 64 + rl) v = -1e30f;
                Ps[rl * PST + kl] = v;
            }
        }
        __syncthreads();

        // --- online softmax stats: warp handles 8 rows ---
#pragma unroll
        for (int rr = 0; rr < 8; rr++) {
            int row = (warp << 3) + rr;
            float s1 = Ps[row * PST + lane];
            float s2 = Ps[row * PST + lane + 32];
            float mx = fmaxf(s1, s2);
#pragma unroll
            for (int o = 16; o > 0; o >>= 1)
                mx = fmaxf(mx, __shfl_xor_sync(0xffffffffu, mx, o));
            float mo = m_s[row];
            float mn = fmaxf(mo, mx);
            float a = __expf(mo - mn);
            float p1 = __expf(s1 - mn);
            float p2 = __expf(s2 - mn);
            Ps[row * PST + lane] = p1;
            Ps[row * PST + lane + 32] = p2;
            float sum = p1 + p2;
#pragma unroll
            for (int o = 16; o > 0; o >>= 1)
                sum += __shfl_xor_sync(0xffffffffu, sum, o);
            if (lane == 0) {
                m_s[row] = mn;
                l_s[row] = l_s[row] * a + sum;
                al_s[row] = a;
            }
        }
        __syncthreads();

        // --- rescale + P@V : warp covers 16 rows x 64 d; lane 4x8 ---
#pragma unroll
        for (int i = 0; i < 4; i++) {
            float a = al_s[wr * 16 + i * 4 + lr];
#pragma unroll
            for (int j = 0; j < 8; j++) acc[i][j] *= a;
        }
#pragma unroll 4
        for (int k = 0; k < 64; k++) {
            float4 v0 = *(const float4*)&Vs[k * QST + d0];
            float4 v1 = *(const float4*)&Vs[k * QST + d0 + 4];
#pragma unroll
            for (int i = 0; i < 4; i++) {
                float p = Ps[(wr * 16 + i * 4 + lr) * PST + k];
                acc[i][0] += p * v0.x; acc[i][1] += p * v0.y;
                acc[i][2] += p * v0.z; acc[i][3] += p * v0.w;
                acc[i][4] += p * v1.x; acc[i][5] += p * v1.y;
                acc[i][6] += p * v1.z; acc[i][7] += p * v1.w;
            }
        }
        __syncthreads();
    }

    // epilogue: O = acc/l, written tf32-rounded for the output GEMM
#pragma unroll
    for (int i = 0; i < 4; i++) {
        int rl = wr * 16 + i * 4 + lr;
        float inv = 1.0f / l_s[rl];
        size_t off = (size_t)(tBase + rl) * QDIM + (size_t)h * HD + d0;
        float4 o0, o1;
        o0.x = tf32r(acc[i][0] * inv); o0.y = tf32r(acc[i][1] * inv);
        o0.z = tf32r(acc[i][2] * inv); o0.w = tf32r(acc[i][3] * inv);
        o1.x = tf32r(acc[i][4] * inv); o1.y = tf32r(acc[i][5] * inv);
        o1.z = tf32r(acc[i][6] * inv); o1.w = tf32r(acc[i][7] * inv);
        *(float4*)&g_ao[off]     = o0;
        *(float4*)&g_ao[off + 4] = o1;
    }
}

// ---------------- launch ----------------
#define GEMM_SMEM ((2 * GBM * AST + 2 * GBK * BST) * 4)

extern "C" void kernel_launch(void* const* d_in, const int* in_sizes, int n_in,
                              void* d_out, int out_size) {
    const float* hid = (const float*)d_in[0];
    const int*   pos = (const int*)d_in[1];     // int32 or int64 (auto-detected)
    const float* Wq  = (const float*)d_in[2];
    const float* Wk  = (const float*)d_in[3];
    const float* Wv  = (const float*)d_in[4];
    const float* Wo  = (const float*)d_in[5];
    const float* qw  = (const float*)d_in[6];
    const float* kw  = (const float*)d_in[7];
    float* out = (float*)d_out;

    float *hid_r, *wq_r, *wk_r, *wv_r, *wo_r, *qb, *kb, *vb, *ao;
    cudaGetSymbolAddress((void**)&hid_r, g_hid_r);
    cudaGetSymbolAddress((void**)&wq_r, g_Wq_r);
    cudaGetSymbolAddress((void**)&wk_r, g_Wk_r);
    cudaGetSymbolAddress((void**)&wv_r, g_Wv_r);
    cudaGetSymbolAddress((void**)&wo_r, g_Wo_r);
    cudaGetSymbolAddress((void**)&qb, g_q);
    cudaGetSymbolAddress((void**)&kb, g_k);
    cudaGetSymbolAddress((void**)&vb, g_v);
    cudaGetSymbolAddress((void**)&ao, g_ao);

    cudaFuncSetAttribute(gemm_tf32_kernel, cudaFuncAttributeMaxDynamicSharedMemorySize, GEMM_SMEM);
    cudaFuncSetAttribute(attn_kernel, cudaFuncAttributeMaxDynamicSharedMemorySize, ATTN_SMEM);

    // tf32 pre-rounding
    {
        int n4;
        n4 = T_TOK * HIDN / 4;
        round4_kernel<<<(n4 + 255) / 256, 256>>>((const float4*)hid, (float4*)hid_r, n4);
        n4 = HIDN * QDIM / 4;
        round4_kernel<<<(n4 + 255) / 256, 256>>>((const float4*)Wq, (float4*)wq_r, n4);
        n4 = HIDN * KVDIM / 4;
        round4_kernel<<<(n4 + 255) / 256, 256>>>((const float4*)Wk, (float4*)wk_r, n4);
        round4_kernel<<<(n4 + 255) / 256, 256>>>((const float4*)Wv, (float4*)wv_r, n4);
        n4 = QDIM * HIDN / 4;
        round4_kernel<<<(n4 + 255) / 256, 256>>>((const float4*)Wo, (float4*)wo_r, n4);
    }

    rope_table_kernel<<<(T_TOK * 64) / 256, 256>>>(pos);

    // QKV projections
    {
        dim3 gq(QDIM / GBN, T_TOK / GBM);
        gemm_tf32_kernel<<<gq, 256, GEMM_SMEM>>>(hid_r, wq_r, qb, T_TOK, QDIM, HIDN);
        dim3 gk(KVDIM / GBN, T_TOK / GBM);
        gemm_tf32_kernel<<<gk, 256, GEMM_SMEM>>>(hid_r, wk_r, kb, T_TOK, KVDIM, HIDN);
        gemm_tf32_kernel<<<gk, 256, GEMM_SMEM>>>(hid_r, wv_r, vb, T_TOK, KVDIM, HIDN);
    }

    norm_rope_kernel<<<T_TOK * (NH + NKV), 128>>>(qw, kw);

    {
        dim3 ga(SEQ / 64, NH, BATCH);
        attn_kernel<<<ga, 256, ATTN_SMEM>>>();
    }

    // output projection -> d_out
    {
        dim3 go(HIDN / GBN, T_TOK / GBM);
        gemm_tf32_kernel<<<go, 256, GEMM_SMEM>>>(ao, wo_r, out, T_TOK, HIDN, QDIM);
    }
}

// round 2
// speedup vs baseline: 1.8861x; 1.8861x over previous
#include <cuda_runtime.h>
#include <math.h>
#include <stdint.h>

// ---------------- problem constants ----------------
#define BATCH 2
#define SEQ   2048
#define T_TOK 4096          // BATCH*SEQ
#define HIDN  2560
#define NH    32
#define NKV   8
#define HD    128
#define QDIM  4096          // NH*HD
#define KVDIM 1024          // NKV*HD

// ---------------- scratch ----------------
__device__ float g_hid_r[(size_t)T_TOK * HIDN];
__device__ float g_Wq_r[(size_t)HIDN * QDIM];
__device__ float g_Wk_r[(size_t)HIDN * KVDIM];
__device__ float g_Wv_r[(size_t)HIDN * KVDIM];
__device__ float g_Wo_r[(size_t)QDIM * HIDN];
__device__ float g_q[(size_t)T_TOK * QDIM];
__device__ float g_k[(size_t)T_TOK * KVDIM];
__device__ float g_v[(size_t)T_TOK * KVDIM];
__device__ float g_ao[(size_t)T_TOK * QDIM];
__device__ float g_cos[(size_t)T_TOK * 64];
__device__ float g_sin[(size_t)T_TOK * 64];

// ---------------- helpers ----------------
__device__ __forceinline__ float tf32r(float x) {
    unsigned u;
    asm("cvt.rna.tf32.f32 %0, %1;" : "=r"(u) : "f"(x));
    return __uint_as_float(u);
}

__device__ __forceinline__ void cp16(void* smem_dst, const void* gsrc) {
    unsigned d = (unsigned)__cvta_generic_to_shared(smem_dst);
    asm volatile("cp.async.cg.shared.global [%0], [%1], 16;\n" :: "r"(d), "l"(gsrc));
}

__device__ __forceinline__ void mma_tf32(
    float& d0, float& d1, float& d2, float& d3,
    unsigned a0, unsigned a1, unsigned a2, unsigned a3,
    unsigned b0, unsigned b1)
{
    asm volatile(
        "mma.sync.aligned.m16n8k8.row.col.f32.tf32.tf32.f32 "
        "{%0,%1,%2,%3},{%4,%5,%6,%7},{%8,%9},{%0,%1,%2,%3};"
        : "+f"(d0), "+f"(d1), "+f"(d2), "+f"(d3)
        : "r"(a0), "r"(a1), "r"(a2), "r"(a3), "r"(b0), "r"(b1));
}

// ---------------- tf32 round pass ----------------
__global__ void round4_kernel(const float4* __restrict__ in, float4* __restrict__ out, int n4) {
    int i = blockIdx.x * blockDim.x + threadIdx.x;
    int stride = gridDim.x * blockDim.x;
    for (; i < n4; i += stride) {
        float4 v = in[i];
        v.x = tf32r(v.x); v.y = tf32r(v.y); v.z = tf32r(v.z); v.w = tf32r(v.w);
        out[i] = v;
    }
}

// ---------------- RoPE cos/sin table ----------------
__global__ void rope_table_kernel(const int* __restrict__ p32) {
    int idx = blockIdx.x * blockDim.x + threadIdx.x;
    if (idx >= T_TOK * 64) return;
    int t = idx >> 6;
    int i = idx & 63;
    bool is64 = (p32[1] == 0 && p32[2] == 1);
    int pos = is64 ? p32[2 * t] : p32[t];
    double ang = (double)pos * exp(-(double)i * (log(1000000.0) / 64.0));
    g_cos[idx] = (float)cos(ang);
    g_sin[idx] = (float)sin(ang);
}

// ---------------- tf32 mma GEMM: C[M,N] = A[M,K] @ B[K,N] ----------------
#define GBM 128
#define GBN 128
#define GBK 32
#define AST 36
#define BST 136

__device__ __forceinline__ void gemm_load_tiles(
    const float* __restrict__ A, const float* __restrict__ B,
    int N, int K, int mBase, int nBase, int kt,
    float* As, float* Bs, int tid)
{
    const float* Ag = A + (size_t)mBase * K + (size_t)kt * GBK;
#pragma unroll
    for (int i = 0; i < 4; i++) {
        int e = tid + i * 256;
        int r = e >> 3, ks = (e & 7) << 2;
        cp16(&As[r * AST + ks], Ag + (size_t)r * K + ks);
    }
    const float* Bg = B + (size_t)(kt * GBK) * N + nBase;
#pragma unroll
    for (int i = 0; i < 4; i++) {
        int e = tid + i * 256;
        int r = e >> 5, ns = (e & 31) << 2;
        cp16(&Bs[r * BST + ns], Bg + (size_t)r * N + ns);
    }
    asm volatile("cp.async.commit_group;\n");
}

__global__ void __launch_bounds__(256) gemm_tf32_kernel(
    const float* __restrict__ A, const float* __restrict__ B, float* __restrict__ C,
    int M, int N, int K)
{
    extern __shared__ float smem[];
    float* As = smem;
    float* Bs = smem + 2 * GBM * AST;

    const int tid = threadIdx.x;
    const int warp = tid >> 5, lane = tid & 31;
    const int wm = warp >> 2, wn = warp & 3;
    const int g = lane >> 2, tq = lane & 3;
    const int mBase = blockIdx.y * GBM;
    const int nBase = blockIdx.x * GBN;

    float c[4][4][4];
#pragma unroll
    for (int a = 0; a < 4; a++)
#pragma unroll
        for (int bq = 0; bq < 4; bq++)
#pragma unroll
            for (int e = 0; e < 4; e++) c[a][bq][e] = 0.f;

    const int KT = K / GBK;
    gemm_load_tiles(A, B, N, K, mBase, nBase, 0, As, Bs, tid);

    for (int kt = 0; kt < KT; kt++) {
        float* as = As + (kt & 1) * GBM * AST;
        float* bs = Bs + (kt & 1) * GBK * BST;
        if (kt + 1 < KT) {
            gemm_load_tiles(A, B, N, K, mBase, nBase, kt + 1,
                            As + ((kt + 1) & 1) * GBM * AST,
                            Bs + ((kt + 1) & 1) * GBK * BST, tid);
            asm volatile("cp.async.wait_group 1;\n");
        } else {
            asm volatile("cp.async.wait_group 0;\n");
        }
        __syncthreads();

#pragma unroll
        for (int ks = 0; ks < 4; ks++) {
            const int k0 = ks * 8;
            unsigned af[4][4];
            unsigned bf[4][2];
#pragma unroll
            for (int mt = 0; mt < 4; mt++) {
                int r0 = wm * 64 + mt * 16;
                af[mt][0] = __float_as_uint(as[(r0 + g)     * AST + k0 + tq]);
                af[mt][1] = __float_as_uint(as[(r0 + g + 8) * AST + k0 + tq]);
                af[mt][2] = __float_as_uint(as[(r0 + g)     * AST + k0 + tq + 4]);
                af[mt][3] = __float_as_uint(as[(r0 + g + 8) * AST + k0 + tq + 4]);
            }
#pragma unroll
            for (int nt = 0; nt < 4; nt++) {
                int c0 = wn * 32 + nt * 8;
                bf[nt][0] = __float_as_uint(bs[(k0 + tq)     * BST + c0 + g]);
                bf[nt][1] = __float_as_uint(bs[(k0 + tq + 4) * BST + c0 + g]);
            }
#pragma unroll
            for (int mt = 0; mt < 4; mt++)
#pragma unroll
                for (int nt = 0; nt < 4; nt++)
                    mma_tf32(c[mt][nt][0], c[mt][nt][1], c[mt][nt][2], c[mt][nt][3],
                             af[mt][0], af[mt][1], af[mt][2], af[mt][3],
                             bf[nt][0], bf[nt][1]);
        }
        __syncthreads();
    }

#pragma unroll
    for (int mt = 0; mt < 4; mt++) {
        int r0 = mBase + wm * 64 + mt * 16;
#pragma unroll
        for (int nt = 0; nt < 4; nt++) {
            int c0 = nBase + wn * 32 + nt * 8 + tq * 2;
            *(float2*)&C[(size_t)(r0 + g)     * N + c0] = make_float2(c[mt][nt][0], c[mt][nt][1]);
            *(float2*)&C[(size_t)(r0 + g + 8) * N + c0] = make_float2(c[mt][nt][2], c[mt][nt][3]);
        }
    }
}

// ---------------- fused RMSNorm + RoPE (writes tf32-rounded) ----------------
__global__ void __launch_bounds__(128) norm_rope_kernel(
    const float* __restrict__ qw, const float* __restrict__ kw)
{
    int rid = blockIdx.x;
    int tid = threadIdx.x;
    float* buf;
    const float* w;
    int t;
    if (rid < T_TOK * NH) {
        t = rid / NH;
        int h = rid % NH;
        buf = g_q + (size_t)t * QDIM + (size_t)h * HD;
        w = qw;
    } else {
        rid -= T_TOK * NH;
        t = rid / NKV;
        int h = rid % NKV;
        buf = g_k + (size_t)t * KVDIM + (size_t)h * HD;
        w = kw;
    }
    float x = buf[tid];
    float s = x * x;
#pragma unroll
    for (int o = 16; o > 0; o >>= 1) s += __shfl_xor_sync(0xffffffffu, s, o);
    __shared__ float ws[4];
    __shared__ float sh[128];
    if ((tid & 31) == 0) ws[tid >> 5] = s;
    __syncthreads();
    s = ws[0] + ws[1] + ws[2] + ws[3];
    float y = x * rsqrtf(s * (1.0f / 128.0f) + 1e-6f) * w[tid];
    sh[tid] = y;
    __syncthreads();
    float c = g_cos[(size_t)t * 64 + (tid & 63)];
    float sn = g_sin[(size_t)t * 64 + (tid & 63)];
    float rot = (tid < 64) ? -sh[tid + 64] : sh[tid - 64];
    buf[tid] = tf32r(y * c + rot * sn);
}

// ---------------- tensor-core flash attention (tf32 mma) ----------------
// Block: 128 q rows x one head. 8 warps, each owns 16 q rows x all 64 k cols.
// K-tiles of 64. Softmax fully warp-local; P via per-warp padded smem.
#define AQST 132   // Q smem stride  (4g+tq bank pattern)
#define AKST 132   // K smem stride  (4g+tq)
#define AVST 136   // V smem stride  (8tq+g)
#define APST 68    // P smem stride  (4g+tq)
#define ATT_SMEM ((128*AQST + 64*AKST + 64*AVST + 8*16*APST) * 4)

__global__ void __launch_bounds__(256) attn_tc_kernel() {
    extern __shared__ float sm[];
    float* Qs = sm;                        // [128][132]
    float* Ks = Qs + 128 * AQST;           // [64][132]
    float* Vs = Ks + 64 * AKST;            // [64][136]
    float* Pw = Vs + 64 * AVST;            // 8 x [16][68]

    const int qt = blockIdx.x, h = blockIdx.y, b = blockIdx.z;
    const int kvh = h >> 2;
    const int tid = threadIdx.x;
    const int warp = tid >> 5, lane = tid & 31;
    const int g = lane >> 2, tq = lane & 3;
    const int tBase = b * SEQ + qt * 128;
    const float scale = 0.08838834764831845f;

    float* Ps = Pw + warp * 16 * APST;
    const int rloc0 = warp * 16 + g;       // local row (and +8)
    const int grow0 = qt * 128 + rloc0;    // global q row

    // issue Q tile loads
#pragma unroll
    for (int i = 0; i < 16; i++) {
        int e = tid + (i << 8);
        int r = e >> 5, ds = (e & 31) << 2;
        cp16(&Qs[r * AQST + ds], &g_q[(size_t)(tBase + r) * QDIM + (size_t)h * HD + ds]);
    }
    asm volatile("cp.async.commit_group;\n");

    float m0 = -1e30f, m1 = -1e30f, l0 = 0.f, l1 = 0.f;
    float o[16][4];
#pragma unroll
    for (int nt = 0; nt < 16; nt++)
#pragma unroll
        for (int e = 0; e < 4; e++) o[nt][e] = 0.f;

    const int nkt = 2 * qt + 2;
    for (int kt = 0; kt < nkt; kt++) {
        if (kt) __syncthreads();   // protect Ks/Vs from overwrite
        const int kBase = b * SEQ + kt * 64;
#pragma unroll
        for (int i = 0; i < 8; i++) {
            int e = tid + (i << 8);
            int r = e >> 5, ds = (e & 31) << 2;
            const size_t go = (size_t)(kBase + r) * KVDIM + (size_t)kvh * HD + ds;
            cp16(&Ks[r * AKST + ds], &g_k[go]);
            cp16(&Vs[r * AVST + ds], &g_v[go]);
        }
        asm volatile("cp.async.commit_group;\n");
        asm volatile("cp.async.wait_group 0;\n");
        __syncthreads();

        // ---- S = Q K^T  (warp: 16 rows x 64 cols) ----
        float s[8][4];
#pragma unroll
        for (int nt = 0; nt < 8; nt++)
#pragma unroll
            for (int e = 0; e < 4; e++) s[nt][e] = 0.f;

#pragma unroll
        for (int ks = 0; ks < 16; ks++) {
            const int k0 = ks * 8;
            unsigned a0 = __float_as_uint(Qs[(rloc0)     * AQST + k0 + tq]);
            unsigned a1 = __float_as_uint(Qs[(rloc0 + 8) * AQST + k0 + tq]);
            unsigned a2 = __float_as_uint(Qs[(rloc0)     * AQST + k0 + tq + 4]);
            unsigned a3 = __float_as_uint(Qs[(rloc0 + 8) * AQST + k0 + tq + 4]);
#pragma unroll
            for (int nt = 0; nt < 8; nt++) {
                int c0 = nt * 8;
                unsigned b0 = __float_as_uint(Ks[(c0 + g) * AKST + k0 + tq]);
                unsigned b1 = __float_as_uint(Ks[(c0 + g) * AKST + k0 + tq + 4]);
                mma_tf32(s[nt][0], s[nt][1], s[nt][2], s[nt][3], a0, a1, a2, a3, b0, b1);
            }
        }

        // ---- scale + causal mask ----
        const bool edge = (kt >= nkt - 2);
#pragma unroll
        for (int nt = 0; nt < 8; nt++) {
            int c0 = kt * 64 + nt * 8 + tq * 2;
            s[nt][0] *= scale; s[nt][1] *= scale;
            s[nt][2] *= scale; s[nt][3] *= scale;
            if (edge) {
                if (c0     > grow0)     s[nt][0] = -1e30f;
                if (c0 + 1 > grow0)     s[nt][1] = -1e30f;
                if (c0     > grow0 + 8) s[nt][2] = -1e30f;
                if (c0 + 1 > grow0 + 8) s[nt][3] = -1e30f;
            }
        }

        // ---- online softmax (rows g, g+8; reduce over quad lanes) ----
        float mx0 = -1e30f, mx1 = -1e30f;
#pragma unroll
        for (int nt = 0; nt < 8; nt++) {
            mx0 = fmaxf(mx0, fmaxf(s[nt][0], s[nt][1]));
            mx1 = fmaxf(mx1, fmaxf(s[nt][2], s[nt][3]));
        }
        mx0 = fmaxf(mx0, __shfl_xor_sync(0xffffffffu, mx0, 1));
        mx0 = fmaxf(mx0, __shfl_xor_sync(0xffffffffu, mx0, 2));
        mx1 = fmaxf(mx1, __shfl_xor_sync(0xffffffffu, mx1, 1));
        mx1 = fmaxf(mx1, __shfl_xor_sync(0xffffffffu, mx1, 2));

        float mn0 = fmaxf(m0, mx0), mn1 = fmaxf(m1, mx1);
        float al0 = __expf(m0 - mn0), al1 = __expf(m1 - mn1);
        m0 = mn0; m1 = mn1;

        float ps0 = 0.f, ps1 = 0.f;
#pragma unroll
        for (int nt = 0; nt < 8; nt++) {
            float p0 = __expf(s[nt][0] - mn0);
            float p1 = __expf(s[nt][1] - mn0);
            float p2 = __expf(s[nt][2] - mn1);
            float p3 = __expf(s[nt][3] - mn1);
            ps0 += p0 + p1; ps1 += p2 + p3;
            int c0 = nt * 8 + tq * 2;
            *(float2*)&Ps[(g)     * APST + c0] = make_float2(tf32r(p0), tf32r(p1));
            *(float2*)&Ps[(g + 8) * APST + c0] = make_float2(tf32r(p2), tf32r(p3));
        }
        ps0 += __shfl_xor_sync(0xffffffffu, ps0, 1);
        ps0 += __shfl_xor_sync(0xffffffffu, ps0, 2);
        ps1 += __shfl_xor_sync(0xffffffffu, ps1, 1);
        ps1 += __shfl_xor_sync(0xffffffffu, ps1, 2);
        l0 = l0 * al0 + ps0;
        l1 = l1 * al1 + ps1;

        // rescale output accumulators
#pragma unroll
        for (int nt = 0; nt < 16; nt++) {
            o[nt][0] *= al0; o[nt][1] *= al0;
            o[nt][2] *= al1; o[nt][3] *= al1;
        }
        __syncwarp();

        // ---- O += P V  (warp: 16 rows x 128 d-cols) ----
#pragma unroll
        for (int ks = 0; ks < 8; ks++) {
            const int k0 = ks * 8;
            unsigned a0 = __float_as_uint(Ps[(g)     * APST + k0 + tq]);
            unsigned a1 = __float_as_uint(Ps[(g + 8) * APST + k0 + tq]);
            unsigned a2 = __float_as_uint(Ps[(g)     * APST + k0 + tq + 4]);
            unsigned a3 = __float_as_uint(Ps[(g + 8) * APST + k0 + tq + 4]);
#pragma unroll
            for (int nt = 0; nt < 16; nt++) {
                int c0 = nt * 8;
                unsigned b0 = __float_as_uint(Vs[(k0 + tq)     * AVST + c0 + g]);
                unsigned b1 = __float_as_uint(Vs[(k0 + tq + 4) * AVST + c0 + g]);
                mma_tf32(o[nt][0], o[nt][1], o[nt][2], o[nt][3], a0, a1, a2, a3, b0, b1);
            }
        }
    }

    // ---- epilogue: normalize, tf32-round, write ----
    float inv0 = 1.0f / l0, inv1 = 1.0f / l1;
    const size_t r0off = (size_t)(tBase + rloc0) * QDIM + (size_t)h * HD;
    const size_t r1off = r0off + 8 * QDIM;
#pragma unroll
    for (int nt = 0; nt < 16; nt++) {
        int c0 = nt * 8 + tq * 2;
        *(float2*)&g_ao[r0off + c0] = make_float2(tf32r(o[nt][0] * inv0), tf32r(o[nt][1] * inv0));
        *(float2*)&g_ao[r1off + c0] = make_float2(tf32r(o[nt][2] * inv1), tf32r(o[nt][3] * inv1));
    }
}

// ---------------- launch ----------------
#define GEMM_SMEM ((2 * GBM * AST + 2 * GBK * BST) * 4)

extern "C" void kernel_launch(void* const* d_in, const int* in_sizes, int n_in,
                              void* d_out, int out_size) {
    const float* hid = (const float*)d_in[0];
    const int*   pos = (const int*)d_in[1];
    const float* Wq  = (const float*)d_in[2];
    const float* Wk  = (const float*)d_in[3];
    const float* Wv  = (const float*)d_in[4];
    const float* Wo  = (const float*)d_in[5];
    const float* qw  = (const float*)d_in[6];
    const float* kw  = (const float*)d_in[7];
    float* out = (float*)d_out;

    float *hid_r, *wq_r, *wk_r, *wv_r, *wo_r, *qb, *kb, *vb, *ao;
    cudaGetSymbolAddress((void**)&hid_r, g_hid_r);
    cudaGetSymbolAddress((void**)&wq_r, g_Wq_r);
    cudaGetSymbolAddress((void**)&wk_r, g_Wk_r);
    cudaGetSymbolAddress((void**)&wv_r, g_Wv_r);
    cudaGetSymbolAddress((void**)&wo_r, g_Wo_r);
    cudaGetSymbolAddress((void**)&qb, g_q);
    cudaGetSymbolAddress((void**)&kb, g_k);
    cudaGetSymbolAddress((void**)&vb, g_v);
    cudaGetSymbolAddress((void**)&ao, g_ao);

    cudaFuncSetAttribute(gemm_tf32_kernel, cudaFuncAttributeMaxDynamicSharedMemorySize, GEMM_SMEM);
    cudaFuncSetAttribute(attn_tc_kernel, cudaFuncAttributeMaxDynamicSharedMemorySize, ATT_SMEM);

    // tf32 pre-rounding
    {
        int n4;
        n4 = T_TOK * HIDN / 4;
        round4_kernel<<<(n4 + 255) / 256, 256>>>((const float4*)hid, (float4*)hid_r, n4);
        n4 = HIDN * QDIM / 4;
        round4_kernel<<<(n4 + 255) / 256, 256>>>((const float4*)Wq, (float4*)wq_r, n4);
        n4 = HIDN * KVDIM / 4;
        round4_kernel<<<(n4 + 255) / 256, 256>>>((const float4*)Wk, (float4*)wk_r, n4);
        round4_kernel<<<(n4 + 255) / 256, 256>>>((const float4*)Wv, (float4*)wv_r, n4);
        n4 = QDIM * HIDN / 4;
        round4_kernel<<<(n4 + 255) / 256, 256>>>((const float4*)Wo, (float4*)wo_r, n4);
    }

    rope_table_kernel<<<(T_TOK * 64) / 256, 256>>>(pos);

    // QKV projections
    {
        dim3 gq(QDIM / GBN, T_TOK / GBM);
        gemm_tf32_kernel<<<gq, 256, GEMM_SMEM>>>(hid_r, wq_r, qb, T_TOK, QDIM, HIDN);
        dim3 gk(KVDIM / GBN, T_TOK / GBM);
        gemm_tf32_kernel<<<gk, 256, GEMM_SMEM>>>(hid_r, wk_r, kb, T_TOK, KVDIM, HIDN);
        gemm_tf32_kernel<<<gk, 256, GEMM_SMEM>>>(hid_r, wv_r, vb, T_TOK, KVDIM, HIDN);
    }

    norm_rope_kernel<<<T_TOK * (NH + NKV), 128>>>(qw, kw);

    // round V to tf32 in place
    {
        int n4 = T_TOK * KVDIM / 4;
        round4_kernel<<<(n4 + 255) / 256, 256>>>((const float4*)vb, (float4*)vb, n4);
    }

    // tensor-core attention
    {
        dim3 ga(SEQ / 128, NH, BATCH);
        attn_tc_kernel<<<ga, 256, ATT_SMEM>>>();
    }

    // output projection -> d_out
    {
        dim3 go(HIDN / GBN, T_TOK / GBM);
        gemm_tf32_kernel<<<go, 256, GEMM_SMEM>>>(ao, wo_r, out, T_TOK, HIDN, QDIM);
    }
}

// round 4
// speedup vs baseline: 1.9230x; 1.0196x over previous
#include <cuda_runtime.h>
#include <math.h>
#include <stdint.h>

// ---------------- problem constants ----------------
#define BATCH 2
#define SEQ   2048
#define T_TOK 4096
#define HIDN  2560
#define NH    32
#define NKV   8
#define HD    128
#define QDIM  4096
#define KVDIM 1024
#define QKVS  6144          // packed q|k|v row stride

// ---------------- scratch ----------------
__device__ float g_hid_r[(size_t)T_TOK * HIDN];
__device__ float g_WtAll[(size_t)QKVS * HIDN];   // WqT|WkT|WvT rows, each [*, 2560] K-major
__device__ float g_WoT[(size_t)HIDN * QDIM];     // WoT [2560][4096] K-major
__device__ float g_qkv[(size_t)T_TOK * QKVS];
__device__ float g_vT[(size_t)BATCH * NKV * HD * SEQ];  // [b][kv][d][s]
__device__ float g_ao[(size_t)T_TOK * QDIM];
__device__ float g_cos[(size_t)T_TOK * 64];
__device__ float g_sin[(size_t)T_TOK * 64];

// ---------------- helpers ----------------
__device__ __forceinline__ float tf32r(float x) {
    unsigned u;
    asm("cvt.rna.tf32.f32 %0, %1;" : "=r"(u) : "f"(x));
    return __uint_as_float(u);
}

__device__ __forceinline__ uint32_t smem_u32(const void* p) {
    uint32_t a;
    asm("{ .reg .u64 t; cvta.to.shared.u64 t, %1; cvt.u32.u64 %0, t; }" : "=r"(a) : "l"(p));
    return a;
}

__device__ __forceinline__ void cp16s(uint32_t saddr, const void* gsrc) {
    asm volatile("cp.async.cg.shared.global [%0], [%1], 16;\n" :: "r"(saddr), "l"(gsrc));
}

__device__ __forceinline__ void ldsm4(unsigned& r0, unsigned& r1, unsigned& r2, unsigned& r3,
                                      uint32_t addr) {
    asm volatile("ldmatrix.sync.aligned.m8n8.x4.shared.b16 {%0,%1,%2,%3}, [%4];"
                 : "=r"(r0), "=r"(r1), "=r"(r2), "=r"(r3) : "r"(addr));
}

__device__ __forceinline__ void mma_tf32(
    float& d0, float& d1, float& d2, float& d3,
    unsigned a0, unsigned a1, unsigned a2, unsigned a3,
    unsigned b0, unsigned b1)
{
    asm volatile(
        "mma.sync.aligned.m16n8k8.row.col.f32.tf32.tf32.f32 "
        "{%0,%1,%2,%3},{%4,%5,%6,%7},{%8,%9},{%0,%1,%2,%3};"
        : "+f"(d0), "+f"(d1), "+f"(d2), "+f"(d3)
        : "r"(a0), "r"(a1), "r"(a2), "r"(a3), "r"(b0), "r"(b1));
}

// ---------------- tf32 round pass ----------------
__global__ void round4_kernel(const float4* __restrict__ in, float4* __restrict__ out, int n4) {
    int i = blockIdx.x * blockDim.x + threadIdx.x;
    int stride = gridDim.x * blockDim.x;
    for (; i < n4; i += stride) {
        float4 v = in[i];
        v.x = tf32r(v.x); v.y = tf32r(v.y); v.z = tf32r(v.z); v.w = tf32r(v.w);
        out[i] = v;
    }
}

// ---------------- transpose + tf32 round: in [R][C] -> out [C][R] ----------------
__global__ void __launch_bounds__(256) transpose_round_kernel(
    const float* __restrict__ in, float* __restrict__ out, int R, int C)
{
    __shared__ float t[32][33];
    int bc = blockIdx.x * 32, br = blockIdx.y * 32;
    int tx = threadIdx.x, ty = threadIdx.y;   // 32 x 8
#pragma unroll
    for (int i = 0; i < 32; i += 8)
        t[ty + i][tx] = in[(size_t)(br + ty + i) * C + bc + tx];
    __syncthreads();
#pragma unroll
    for (int i = 0; i < 32; i += 8)
        out[(size_t)(bc + ty + i) * R + br + tx] = tf32r(t[tx][ty + i]);
}

// ---------------- V transpose: g_qkv v-slice [t][d] -> g_vT [b][kv][d][s] + round ----------------
__global__ void __launch_bounds__(256) transpose_v_kernel() {
    __shared__ float t[32][33];
    int z = blockIdx.z;           // b*8 + kv
    int b = z >> 3, kv = z & 7;
    int s0 = blockIdx.x * 32, d0 = blockIdx.y * 32;
    int tx = threadIdx.x, ty = threadIdx.y;
#pragma unroll
    for (int i = 0; i < 32; i += 8)
        t[ty + i][tx] = g_qkv[(size_t)(b * SEQ + s0 + ty + i) * QKVS + 5120 + kv * HD + d0 + tx];
    __syncthreads();
#pragma unroll
    for (int i = 0; i < 32; i += 8)
        g_vT[((size_t)z * HD + d0 + ty + i) * SEQ + s0 + tx] = tf32r(t[tx][ty + i]);
}

// ---------------- RoPE cos/sin table ----------------
__global__ void rope_table_kernel(const int* __restrict__ p32) {
    int idx = blockIdx.x * blockDim.x + threadIdx.x;
    if (idx >= T_TOK * 64) return;
    int t = idx >> 6;
    int i = idx & 63;
    bool is64 = (p32[1] == 0 && p32[2] == 1);
    int pos = is64 ? p32[2 * t] : p32[t];
    double ang = (double)pos * exp(-(double)i * (log(1000000.0) / 64.0));
    g_cos[idx] = (float)cos(ang);
    g_sin[idx] = (float)sin(ang);
}

// ---------------- tf32 mma GEMM via ldmatrix: C[M,N] = A[M,K] @ Bt[N,K]^T ----------------
// Block tile 256x128, K-chunk 32. Both tiles K-major [row][k] in smem, stride 36.
// 8 warps: wm (0..3) x wn (0..1), warp tile 64x64.
#define TM 256
#define TN 128
#define GST 36
#define A_STAGE (TM * GST * 4)                 // 36864 B
#define STAGE_BYTES ((TM + TN) * GST * 4)      // 55296 B
#define GEMM_SMEM (2 * STAGE_BYTES)            // 110592 B

__device__ __forceinline__ void tc_load(
    const float* __restrict__ A, const float* __restrict__ Bt, int K,
    int mBase, int nBase, int kc, uint32_t sA, uint32_t sB, int tid)
{
    const float* Ag = A + (size_t)mBase * K + (size_t)kc * 32;
#pragma unroll
    for (int i = 0; i < 8; i++) {
        int e = tid + i * 256;               // 0..2047: 256 rows x 8 q
        int r = e >> 3, q = (e & 7) << 2;
        cp16s(sA + (uint32_t)(r * GST + q) * 4, Ag + (size_t)r * K + q);
    }
    const float* Bg = Bt + (size_t)nBase * K + (size_t)kc * 32;
#pragma unroll
    for (int i = 0; i < 4; i++) {
        int e = tid + i * 256;               // 0..1023: 128 rows x 8 q
        int r = e >> 3, q = (e & 7) << 2;
        cp16s(sB + (uint32_t)(r * GST + q) * 4, Bg + (size_t)r * K + q);
    }
    asm volatile("cp.async.commit_group;\n");
}

__global__ void __launch_bounds__(256, 1) gemm_tc_kernel(
    const float* __restrict__ A, const float* __restrict__ Bt, float* __restrict__ C,
    int M, int N, int K)
{
    extern __shared__ char smem[];
    const uint32_t sb = smem_u32(smem);
    const int tid = threadIdx.x, warp = tid >> 5, lane = tid & 31;
    const int wm = warp >> 1, wn = warp & 1;
    const int g = lane >> 2, tq = lane & 3;
    const int mBase = blockIdx.y * TM, nBase = blockIdx.x * TN;

    float c[4][8][4];
#pragma unroll
    for (int mt = 0; mt < 4; mt++)
#pragma unroll
        for (int nt = 0; nt < 8; nt++)
#pragma unroll
            for (int e = 0; e < 4; e++) c[mt][nt][e] = 0.f;

    // ldmatrix per-lane fragment offsets
    const uint32_t aFragOff =
        (uint32_t)((wm * 64 + (lane & 15)) * GST) * 4 + ((lane & 16) ? 16u : 0u);
    const uint32_t bFragOff =
        (uint32_t)((wn * 64 + (lane & 7) + ((lane & 16) >> 1)) * GST) * 4 + ((lane & 8) << 1);

    const int nk = K >> 5;
    tc_load(A, Bt, K, mBase, nBase, 0, sb, sb + A_STAGE, tid);

    for (int i = 0; i < nk; i++) {
        const uint32_t stA = sb + (uint32_t)(i & 1) * STAGE_BYTES;
        const uint32_t stB = stA + A_STAGE;
        if (i + 1 < nk) {
            const uint32_t nA = sb + (uint32_t)((i + 1) & 1) * STAGE_BYTES;
            tc_load(A, Bt, K, mBase, nBase, i + 1, nA, nA + A_STAGE, tid);
            asm volatile("cp.async.wait_group 1;\n");
        } else {
            asm volatile("cp.async.wait_group 0;\n");
        }
        __syncthreads();

#pragma unroll
        for (int ks = 0; ks < 4; ks++) {
            unsigned a[4][4], b[4][4];
#pragma unroll
            for (int mt = 0; mt < 4; mt++)
                ldsm4(a[mt][0], a[mt][1], a[mt][2], a[mt][3],
                      stA + aFragOff + (uint32_t)(mt * 16 * GST * 4 + ks * 32));
#pragma unroll
            for (int p = 0; p < 4; p++)
                ldsm4(b[p][0], b[p][1], b[p][2], b[p][3],
                      stB + bFragOff + (uint32_t)(p * 16 * GST * 4 + ks * 32));
#pragma unroll
            for (int mt = 0; mt < 4; mt++)
#pragma unroll
                for (int nt = 0; nt < 8; nt++) {
                    const int p = nt >> 1, idx = (nt & 1) * 2;
                    mma_tf32(c[mt][nt][0], c[mt][nt][1], c[mt][nt][2], c[mt][nt][3],
                             a[mt][0], a[mt][1], a[mt][2], a[mt][3],
                             b[p][idx], b[p][idx + 1]);
                }
        }
        __syncthreads();
    }

    // epilogue
#pragma unroll
    for (int mt = 0; mt < 4; mt++) {
        const int r0 = mBase + wm * 64 + mt * 16;
#pragma unroll
        for (int nt = 0; nt < 8; nt++) {
            const int c0 = nBase + wn * 64 + nt * 8 + tq * 2;
            *(float2*)&C[(size_t)(r0 + g)     * N + c0] = make_float2(c[mt][nt][0], c[mt][nt][1]);
            *(float2*)&C[(size_t)(r0 + g + 8) * N + c0] = make_float2(c[mt][nt][2], c[mt][nt][3]);
        }
    }
}

// ---------------- fused RMSNorm + RoPE (in place on g_qkv q/k slices, tf32-rounded) -------
__global__ void __launch_bounds__(128) norm_rope_kernel(
    const float* __restrict__ qw, const float* __restrict__ kw)
{
    int rid = blockIdx.x;
    int tid = threadIdx.x;
    float* buf;
    const float* w;
    int t;
    if (rid < T_TOK * NH) {
        t = rid / NH;
        int h = rid % NH;
        buf = g_qkv + (size_t)t * QKVS + (size_t)h * HD;
        w = qw;
    } else {
        rid -= T_TOK * NH;
        t = rid / NKV;
        int h = rid % NKV;
        buf = g_qkv + (size_t)t * QKVS + 4096 + (size_t)h * HD;
        w = kw;
    }
    float x = buf[tid];
    float s = x * x;
#pragma unroll
    for (int o = 16; o > 0; o >>= 1) s += __shfl_xor_sync(0xffffffffu, s, o);
    __shared__ float ws[4];
    __shared__ float sh[128];
    if ((tid & 31) == 0) ws[tid >> 5] = s;
    __syncthreads();
    s = ws[0] + ws[1] + ws[2] + ws[3];
    float y = x * rsqrtf(s * (1.0f / 128.0f) + 1e-6f) * w[tid];
    sh[tid] = y;
    __syncthreads();
    float c = g_cos[(size_t)t * 64 + (tid & 63)];
    float sn = g_sin[(size_t)t * 64 + (tid & 63)];
    float rot = (tid < 64) ? -sh[tid + 64] : sh[tid - 64];
    buf[tid] = tf32r(y * c + rot * sn);
}

// ---------------- tensor-core flash attention (tf32 mma + ldmatrix, GQA-shared K/V) -------
// Block: 32 q-positions x 4 heads of one kv-group (= 128 A-rows), K-tiles of 64.
// 8 warps, each owns 16 A-rows. Q/K smem [row][d] stride 132; V smem [d][s] stride 68.
#define AQST 132
#define VST  68
#define PST  68
#define ATT_SMEM ((128*AQST + 64*AQST + 128*VST + 8*16*PST) * 4)

__global__ void __launch_bounds__(256) attn_tc_kernel() {
    extern __shared__ float sm[];
    float* Qs = sm;                        // [128][132]  rows = 4 heads x 32 q
    float* Ks = Qs + 128 * AQST;           // [64][132]   rows = kpos
    float* Vs = Ks + 64 * AQST;            // [128][68]   rows = d, cols = kpos
    float* Pw = Vs + 128 * VST;            // 8 x [16][68]

    const int qt = 63 - blockIdx.x;        // large tiles first
    const int kvh = blockIdx.y, b = blockIdx.z;
    const int tid = threadIdx.x;
    const int warp = tid >> 5, lane = tid & 31;
    const int g = lane >> 2, tq = lane & 3;
    const float scale = 0.08838834764831845f;

    float* Ps = Pw + warp * 16 * PST;
    const int rloc0 = warp * 16 + g;                 // A-row (and +8)
    const int q0 = qt * 32 + (rloc0 & 31);           // global q position
    const int head = kvh * 4 + (rloc0 >> 5);

    // fragment smem addresses
    const uint32_t qAddr = smem_u32(Qs) +
        (uint32_t)((warp * 16 + (lane & 15)) * AQST) * 4 + ((lane & 16) ? 16u : 0u);
    const uint32_t kAddr = smem_u32(Ks) +
        (uint32_t)(((lane & 7) + ((lane & 16) >> 1)) * AQST) * 4 + ((lane & 8) << 1);
    const uint32_t vAddr = smem_u32(Vs) +
        (uint32_t)(((lane & 7) + ((lane & 16) >> 1)) * VST) * 4 + ((lane & 8) << 1);
    const uint32_t pAddr = smem_u32(Ps) +
        (uint32_t)((lane & 15) * PST) * 4 + ((lane & 16) ? 16u : 0u);

    // load Q tile: row r -> head kvh*4 + r/32, qpos qt*32 + r%32
#pragma unroll
    for (int i = 0; i < 16; i++) {
        int e = tid + (i << 8);
        int r = e >> 5, ds = (e & 31) << 2;
        cp16s(smem_u32(&Qs[r * AQST + ds]),
              &g_qkv[(size_t)(b * SEQ + qt * 32 + (r & 31)) * QKVS +
                     (size_t)(kvh * 4 + (r >> 5)) * HD + ds]);
    }
    asm volatile("cp.async.commit_group;\n");

    float m0 = -1e30f, m1 = -1e30f, l0 = 0.f, l1 = 0.f;
    float o[16][4];
#pragma unroll
    for (int nt = 0; nt < 16; nt++)
#pragma unroll
        for (int e = 0; e < 4; e++) o[nt][e] = 0.f;

    const int nkt = (qt * 32 + 31) / 64 + 1;
    for (int kt = 0; kt < nkt; kt++) {
        if (kt) __syncthreads();
        const int kBase = kt * 64;
        // K tile [64 kpos][128 d]
#pragma unroll
        for (int i = 0; i < 8; i++) {
            int e = tid + (i << 8);
            int r = e >> 5, ds = (e & 31) << 2;
            cp16s(smem_u32(&Ks[r * AQST + ds]),
                  &g_qkv[(size_t)(b * SEQ + kBase + r) * QKVS + 4096 + (size_t)kvh * HD + ds]);
        }
        // V tile transposed [128 d][64 kpos]
#pragma unroll
        for (int i = 0; i < 8; i++) {
            int e = tid + (i << 8);
            int r = e >> 4, ds = (e & 15) << 2;
            cp16s(smem_u32(&Vs[r * VST + ds]),
                  &g_vT[((size_t)(b * NKV + kvh) * HD + r) * SEQ + kBase + ds]);
        }
        asm volatile("cp.async.commit_group;\n");
        asm volatile("cp.async.wait_group 0;\n");
        __syncthreads();

        // ---- S = Q K^T : 16 rows x 64 cols per warp ----
        float s[8][4];
#pragma unroll
        for (int nt = 0; nt < 8; nt++)
#pragma unroll
            for (int e = 0; e < 4; e++) s[nt][e] = 0.f;

#pragma unroll
        for (int ks = 0; ks < 16; ks++) {
            unsigned qa[4];
            ldsm4(qa[0], qa[1], qa[2], qa[3], qAddr + (uint32_t)(ks * 32));
#pragma unroll
            for (int p = 0; p < 4; p++) {
                unsigned kb[4];
                ldsm4(kb[0], kb[1], kb[2], kb[3],
                      kAddr + (uint32_t)(p * 16 * AQST * 4 + ks * 32));
                mma_tf32(s[2*p][0], s[2*p][1], s[2*p][2], s[2*p][3],
                         qa[0], qa[1], qa[2], qa[3], kb[0], kb[1]);
                mma_tf32(s[2*p+1][0], s[2*p+1][1], s[2*p+1][2], s[2*p+1][3],
                         qa[0], qa[1], qa[2], qa[3], kb[2], kb[3]);
            }
        }

        // ---- scale + causal mask ----
        const bool edge = (kBase + 63 > qt * 32);
#pragma unroll
        for (int nt = 0; nt < 8; nt++) {
            int c0 = kBase + nt * 8 + tq * 2;
            s[nt][0] *= scale; s[nt][1] *= scale;
            s[nt][2] *= scale; s[nt][3] *= scale;
            if (edge) {
                if (c0     > q0)     s[nt][0] = -1e30f;
                if (c0 + 1 > q0)     s[nt][1] = -1e30f;
                if (c0     > q0 + 8) s[nt][2] = -1e30f;
                if (c0 + 1 > q0 + 8) s[nt][3] = -1e30f;
            }
        }

        // ---- online softmax (rows q0, q0+8; quad reduction) ----
        float mx0 = -1e30f, mx1 = -1e30f;
#pragma unroll
        for (int nt = 0; nt < 8; nt++) {
            mx0 = fmaxf(mx0, fmaxf(s[nt][0], s[nt][1]));
            mx1 = fmaxf(mx1, fmaxf(s[nt][2], s[nt][3]));
        }
        mx0 = fmaxf(mx0, __shfl_xor_sync(0xffffffffu, mx0, 1));
        mx0 = fmaxf(mx0, __shfl_xor_sync(0xffffffffu, mx0, 2));
        mx1 = fmaxf(mx1, __shfl_xor_sync(0xffffffffu, mx1, 1));
        mx1 = fmaxf(mx1, __shfl_xor_sync(0xffffffffu, mx1, 2));

        float mn0 = fmaxf(m0, mx0), mn1 = fmaxf(m1, mx1);
        float al0 = __expf(m0 - mn0), al1 = __expf(m1 - mn1);
        m0 = mn0; m1 = mn1;

        float ps0 = 0.f, ps1 = 0.f;
#pragma unroll
        for (int nt = 0; nt < 8; nt++) {
            float p0 = __expf(s[nt][0] - mn0);
            float p1 = __expf(s[nt][1] - mn0);
            float p2 = __expf(s[nt][2] - mn1);
            float p3 = __expf(s[nt][3] - mn1);
            ps0 += p0 + p1; ps1 += p2 + p3;
            int c0 = nt * 8 + tq * 2;
            *(float2*)&Ps[(g)     * PST + c0] = make_float2(tf32r(p0), tf32r(p1));
            *(float2*)&Ps[(g + 8) * PST + c0] = make_float2(tf32r(p2), tf32r(p3));
        }
        ps0 += __shfl_xor_sync(0xffffffffu, ps0, 1);
        ps0 += __shfl_xor_sync(0xffffffffu, ps0, 2);
        ps1 += __shfl_xor_sync(0xffffffffu, ps1, 1);
        ps1 += __shfl_xor_sync(0xffffffffu, ps1, 2);
        l0 = l0 * al0 + ps0;
        l1 = l1 * al1 + ps1;

#pragma unroll
        for (int nt = 0; nt < 16; nt++) {
            o[nt][0] *= al0; o[nt][1] *= al0;
            o[nt][2] *= al1; o[nt][3] *= al1;
        }
        __syncwarp();

        // ---- O += P V : 16 rows x 128 d per warp ----
#pragma unroll
        for (int ks = 0; ks < 8; ks++) {
            unsigned pa[4];
            ldsm4(pa[0], pa[1], pa[2], pa[3], pAddr + (uint32_t)(ks * 32));
#pragma unroll
            for (int p = 0; p < 8; p++) {
                unsigned vb[4];
                ldsm4(vb[0], vb[1], vb[2], vb[3],
                      vAddr + (uint32_t)(p * 16 * VST * 4 + ks * 32));
                mma_tf32(o[2*p][0], o[2*p][1], o[2*p][2], o[2*p][3],
                         pa[0], pa[1], pa[2], pa[3], vb[0], vb[1]);
                mma_tf32(o[2*p+1][0], o[2*p+1][1], o[2*p+1][2], o[2*p+1][3],
                         pa[0], pa[1], pa[2], pa[3], vb[2], vb[3]);
            }
        }
    }

    // ---- epilogue ----
    float inv0 = 1.0f / l0, inv1 = 1.0f / l1;
    const size_t r0off = (size_t)(b * SEQ + q0) * QDIM + (size_t)head * HD;
    const size_t r1off = r0off + 8 * QDIM;
#pragma unroll
    for (int nt = 0; nt < 16; nt++) {
        int c0 = nt * 8 + tq * 2;
        *(float2*)&g_ao[r0off + c0] = make_float2(tf32r(o[nt][0] * inv0), tf32r(o[nt][1] * inv0));
        *(float2*)&g_ao[r1off + c0] = make_float2(tf32r(o[nt][2] * inv1), tf32r(o[nt][3] * inv1));
    }
}

// ---------------- launch ----------------
extern "C" void kernel_launch(void* const* d_in, const int* in_sizes, int n_in,
                              void* d_out, int out_size) {
    const float* hid = (const float*)d_in[0];
    const int*   pos = (const int*)d_in[1];
    const float* Wq  = (const float*)d_in[2];
    const float* Wk  = (const float*)d_in[3];
    const float* Wv  = (const float*)d_in[4];
    const float* Wo  = (const float*)d_in[5];
    const float* qw  = (const float*)d_in[6];
    const float* kw  = (const float*)d_in[7];
    float* out = (float*)d_out;

    float *hid_r, *wtall, *wot, *qkv, *ao;
    cudaGetSymbolAddress((void**)&hid_r, g_hid_r);
    cudaGetSymbolAddress((void**)&wtall, g_WtAll);
    cudaGetSymbolAddress((void**)&wot, g_WoT);
    cudaGetSymbolAddress((void**)&qkv, g_qkv);
    cudaGetSymbolAddress((void**)&ao, g_ao);

    cudaFuncSetAttribute(gemm_tc_kernel, cudaFuncAttributeMaxDynamicSharedMemorySize, GEMM_SMEM);
    cudaFuncSetAttribute(attn_tc_kernel, cudaFuncAttributeMaxDynamicSharedMemorySize, ATT_SMEM);

    // round hidden to tf32
    {
        int n4 = T_TOK * HIDN / 4;
        round4_kernel<<<(n4 + 255) / 256, 256>>>((const float4*)hid, (float4*)hid_r, n4);
    }
    // transpose+round weights -> K-major
    {
        dim3 blk(32, 8);
        transpose_round_kernel<<<dim3(QDIM / 32, HIDN / 32), blk>>>(Wq, wtall, HIDN, QDIM);
        transpose_round_kernel<<<dim3(KVDIM / 32, HIDN / 32), blk>>>(Wk, wtall + (size_t)4096 * HIDN, HIDN, KVDIM);
        transpose_round_kernel<<<dim3(KVDIM / 32, HIDN / 32), blk>>>(Wv, wtall + (size_t)5120 * HIDN, HIDN, KVDIM);
        transpose_round_kernel<<<dim3(HIDN / 32, QDIM / 32), blk>>>(Wo, wot, QDIM, HIDN);
    }
    rope_table_kernel<<<(T_TOK * 64) / 256, 256>>>(pos);

    // fused QKV projection: [4096,2560] @ [6144,2560]^T -> [4096,6144]
    gemm_tc_kernel<<<dim3(QKVS / TN, T_TOK / TM), 256, GEMM_SMEM>>>(hid_r, wtall, qkv, T_TOK, QKVS, HIDN);

    norm_rope_kernel<<<T_TOK * (NH + NKV), 128>>>(qw, kw);

    // V -> transposed + tf32-rounded [b][kv][d][s]
    transpose_v_kernel<<<dim3(SEQ / 32, HD / 32, BATCH * NKV), dim3(32, 8)>>>();

    // attention
    attn_tc_kernel<<<dim3(64, NKV, BATCH), 256, ATT_SMEM>>>();

    // output projection: [4096,4096] @ [2560,4096]^T -> out [4096,2560]
    gemm_tc_kernel<<<dim3(HIDN / TN, T_TOK / TM), 256, GEMM_SMEM>>>(ao, wot, out, T_TOK, HIDN, QDIM);
}

// round 6
// speedup vs baseline: 3.5285x; 1.8349x over previous
#include <cuda_runtime.h>
#include <cuda_fp16.h>
#include <math.h>
#include <stdint.h>

// ---------------- problem constants ----------------
#define BATCH 2
#define SEQ   2048
#define T_TOK 4096
#define HIDN  2560
#define NH    32
#define NKV   8
#define HD    128
#define QDIM  4096
#define KVDIM 1024
#define QKVS  6144          // packed q|k|v row stride (halves)

// ---------------- scratch ----------------
__device__ __half g_hid_h[(size_t)T_TOK * HIDN];
__device__ __half g_WtAll[(size_t)QKVS * HIDN];   // WqT|WkT|WvT rows, each [*, 2560] K-major
__device__ __half g_WoT[(size_t)HIDN * QDIM];     // WoT [2560][4096] K-major
__device__ __half g_qkv[(size_t)T_TOK * QKVS];
__device__ __half g_ao[(size_t)T_TOK * QDIM];
__device__ float  g_cos[(size_t)T_TOK * 64];
__device__ float  g_sin[(size_t)T_TOK * 64];

// ---------------- helpers ----------------
__device__ __forceinline__ uint32_t smem_u32(const void* p) {
    uint32_t a;
    asm("{ .reg .u64 t; cvta.to.shared.u64 t, %1; cvt.u32.u64 %0, t; }" : "=r"(a) : "l"(p));
    return a;
}

__device__ __forceinline__ void cp16s(uint32_t saddr, const void* gsrc) {
    asm volatile("cp.async.cg.shared.global [%0], [%1], 16;\n" :: "r"(saddr), "l"(gsrc));
}

__device__ __forceinline__ void ldsm4(unsigned& r0, unsigned& r1, unsigned& r2, unsigned& r3,
                                      uint32_t addr) {
    asm volatile("ldmatrix.sync.aligned.m8n8.x4.shared.b16 {%0,%1,%2,%3}, [%4];"
                 : "=r"(r0), "=r"(r1), "=r"(r2), "=r"(r3) : "r"(addr));
}

__device__ __forceinline__ void ldsm4t(unsigned& r0, unsigned& r1, unsigned& r2, unsigned& r3,
                                       uint32_t addr) {
    asm volatile("ldmatrix.sync.aligned.m8n8.x4.trans.shared.b16 {%0,%1,%2,%3}, [%4];"
                 : "=r"(r0), "=r"(r1), "=r"(r2), "=r"(r3) : "r"(addr));
}

// m16n8k16 fp16 mma, fp32 accumulate
__device__ __forceinline__ void mma_f16(
    float& d0, float& d1, float& d2, float& d3,
    unsigned a0, unsigned a1, unsigned a2, unsigned a3,
    unsigned b0, unsigned b1)
{
    asm volatile(
        "mma.sync.aligned.m16n8k16.row.col.f32.f16.f16.f32 "
        "{%0,%1,%2,%3},{%4,%5,%6,%7},{%8,%9},{%0,%1,%2,%3};"
        : "+f"(d0), "+f"(d1), "+f"(d2), "+f"(d3)
        : "r"(a0), "r"(a1), "r"(a2), "r"(a3), "r"(b0), "r"(b1));
}

// ---------------- fp32 -> fp16 conversion ----------------
__global__ void conv_half_kernel(const float4* __restrict__ in, __half2* __restrict__ out, int n4) {
    int i = blockIdx.x * blockDim.x + threadIdx.x;
    int stride = gridDim.x * blockDim.x;
    for (; i < n4; i += stride) {
        float4 v = in[i];
        out[2 * i]     = __floats2half2_rn(v.x, v.y);
        out[2 * i + 1] = __floats2half2_rn(v.z, v.w);
    }
}

// ---------------- transpose + fp16: in [R][C] f32 -> out [C][R] f16 ----------------
__global__ void __launch_bounds__(256) transpose_half_kernel(
    const float* __restrict__ in, __half* __restrict__ out, int R, int C)
{
    __shared__ float t[32][33];
    int bc = blockIdx.x * 32, br = blockIdx.y * 32;
    int tx = threadIdx.x, ty = threadIdx.y;   // 32 x 8
#pragma unroll
    for (int i = 0; i < 32; i += 8)
        t[ty + i][tx] = in[(size_t)(br + ty + i) * C + bc + tx];
    __syncthreads();
#pragma unroll
    for (int i = 0; i < 32; i += 8)
        out[(size_t)(bc + ty + i) * R + br + tx] = __float2half_rn(t[tx][ty + i]);
}

// ---------------- RoPE cos/sin table ----------------
__global__ void rope_table_kernel(const int* __restrict__ p32) {
    int idx = blockIdx.x * blockDim.x + threadIdx.x;
    if (idx >= T_TOK * 64) return;
    int t = idx >> 6;
    int i = idx & 63;
    bool is64 = (p32[1] == 0 && p32[2] == 1);
    int pos = is64 ? p32[2 * t] : p32[t];
    double ang = (double)pos * exp(-(double)i * (log(1000000.0) / 64.0));
    g_cos[idx] = (float)cos(ang);
    g_sin[idx] = (float)sin(ang);
}

// ---------------- fp16 mma GEMM: C[M,N] = A[M,K] @ Bt[N,K]^T ----------------
// Block tile 256x128, K-chunk 64 halves. smem K-major rows, stride 72 halves (144B).
// 8 warps: wm(0..3) x wn(0..1), warp tile 64x64. Per chunk: 4 k16 steps.
#define TM 256
#define TN 128
#define GSTH 72
#define A_STAGE (TM * GSTH * 2)                 // 36864 B
#define STAGE_BYTES ((TM + TN) * GSTH * 2)      // 55296 B
#define GEMM_SMEM (2 * STAGE_BYTES)             // 110592 B

__device__ __forceinline__ void g_load(
    const __half* __restrict__ A, const __half* __restrict__ Bt, int K,
    int mBase, int nBase, int kc, uint32_t sA, uint32_t sB, int tid)
{
    const __half* Ag = A + (size_t)mBase * K + (size_t)kc * 64;
#pragma unroll
    for (int i = 0; i < 8; i++) {
        int e = tid + i * 256;               // 256 rows x 8 chunks
        int r = e >> 3, q = (e & 7) << 3;    // q in halves
        cp16s(sA + (uint32_t)(r * GSTH + q) * 2, Ag + (size_t)r * K + q);
    }
    const __half* Bg = Bt + (size_t)nBase * K + (size_t)kc * 64;
#pragma unroll
    for (int i = 0; i < 4; i++) {
        int e = tid + i * 256;               // 128 rows x 8 chunks
        int r = e >> 3, q = (e & 7) << 3;
        cp16s(sB + (uint32_t)(r * GSTH + q) * 2, Bg + (size_t)r * K + q);
    }
    asm volatile("cp.async.commit_group;\n");
}

template <typename OutT>
__global__ void __launch_bounds__(256, 1) gemm_f16_kernel(
    const __half* __restrict__ A, const __half* __restrict__ Bt, OutT* __restrict__ C,
    int M, int N, int K)
{
    extern __shared__ char smem[];
    const uint32_t sb = smem_u32(smem);
    const int tid = threadIdx.x, warp = tid >> 5, lane = tid & 31;
    const int wm = warp >> 1, wn = warp & 1;
    const int g = lane >> 2, tq = lane & 3;
    const int mBase = blockIdx.y * TM, nBase = blockIdx.x * TN;

    float c[4][8][4];
#pragma unroll
    for (int mt = 0; mt < 4; mt++)
#pragma unroll
        for (int nt = 0; nt < 8; nt++)
#pragma unroll
            for (int e = 0; e < 4; e++) c[mt][nt][e] = 0.f;

    // fragment byte offsets within stage
    const uint32_t aFragOff =
        (uint32_t)((wm * 64 + (lane & 15)) * GSTH) * 2 + ((lane & 16) ? 16u : 0u);
    const uint32_t bFragOff =
        (uint32_t)((wn * 64 + (lane & 7) + ((lane & 16) >> 1)) * GSTH) * 2 + ((lane & 8) << 1);

    const int nk = K >> 6;
    g_load(A, Bt, K, mBase, nBase, 0, sb, sb + A_STAGE, tid);

    for (int i = 0; i < nk; i++) {
        const uint32_t stA = sb + (uint32_t)(i & 1) * STAGE_BYTES;
        const uint32_t stB = stA + A_STAGE;
        if (i + 1 < nk) {
            const uint32_t nA = sb + (uint32_t)((i + 1) & 1) * STAGE_BYTES;
            g_load(A, Bt, K, mBase, nBase, i + 1, nA, nA + A_STAGE, tid);
            asm volatile("cp.async.wait_group 1;\n");
        } else {
            asm volatile("cp.async.wait_group 0;\n");
        }
        __syncthreads();

#pragma unroll
        for (int ks = 0; ks < 4; ks++) {
            unsigned a[4][4], b[4][4];
#pragma unroll
            for (int mt = 0; mt < 4; mt++)
                ldsm4(a[mt][0], a[mt][1], a[mt][2], a[mt][3],
                      stA + aFragOff + (uint32_t)(mt * 16 * GSTH * 2 + ks * 32));
#pragma unroll
            for (int p = 0; p < 4; p++)
                ldsm4(b[p][0], b[p][1], b[p][2], b[p][3],
                      stB + bFragOff + (uint32_t)(p * 16 * GSTH * 2 + ks * 32));
#pragma unroll
            for (int mt = 0; mt < 4; mt++)
#pragma unroll
                for (int nt = 0; nt < 8; nt++) {
                    const int p = nt >> 1, idx = (nt & 1) * 2;
                    mma_f16(c[mt][nt][0], c[mt][nt][1], c[mt][nt][2], c[mt][nt][3],
                            a[mt][0], a[mt][1], a[mt][2], a[mt][3],
                            b[p][idx], b[p][idx + 1]);
                }
        }
        __syncthreads();
    }

    // epilogue
#pragma unroll
    for (int mt = 0; mt < 4; mt++) {
        const int r0 = mBase + wm * 64 + mt * 16;
#pragma unroll
        for (int nt = 0; nt < 8; nt++) {
            const int c0 = nBase + wn * 64 + nt * 8 + tq * 2;
            if constexpr (sizeof(OutT) == 2) {
                *(__half2*)&C[(size_t)(r0 + g)     * N + c0] =
                    __floats2half2_rn(c[mt][nt][0], c[mt][nt][1]);
                *(__half2*)&C[(size_t)(r0 + g + 8) * N + c0] =
                    __floats2half2_rn(c[mt][nt][2], c[mt][nt][3]);
            } else {
                *(float2*)&C[(size_t)(r0 + g)     * N + c0] = make_float2(c[mt][nt][0], c[mt][nt][1]);
                *(float2*)&C[(size_t)(r0 + g + 8) * N + c0] = make_float2(c[mt][nt][2], c[mt][nt][3]);
            }
        }
    }
}

// ---------------- fused RMSNorm + RoPE (in place on half g_qkv q/k slices) ----------------
__global__ void __launch_bounds__(128) norm_rope_kernel(
    const float* __restrict__ qw, const float* __restrict__ kw)
{
    int rid = blockIdx.x;
    int tid = threadIdx.x;
    __half* buf;
    const float* w;
    int t;
    if (rid < T_TOK * NH) {
        t = rid / NH;
        int h = rid % NH;
        buf = g_qkv + (size_t)t * QKVS + (size_t)h * HD;
        w = qw;
    } else {
        rid -= T_TOK * NH;
        t = rid / NKV;
        int h = rid % NKV;
        buf = g_qkv + (size_t)t * QKVS + 4096 + (size_t)h * HD;
        w = kw;
    }
    float x = __half2float(buf[tid]);
    float s = x * x;
#pragma unroll
    for (int o = 16; o > 0; o >>= 1) s += __shfl_xor_sync(0xffffffffu, s, o);
    __shared__ float ws[4];
    __shared__ float sh[128];
    if ((tid & 31) == 0) ws[tid >> 5] = s;
    __syncthreads();
    s = ws[0] + ws[1] + ws[2] + ws[3];
    float y = x * rsqrtf(s * (1.0f / 128.0f) + 1e-6f) * w[tid];
    sh[tid] = y;
    __syncthreads();
    float c = g_cos[(size_t)t * 64 + (tid & 63)];
    float sn = g_sin[(size_t)t * 64 + (tid & 63)];
    float rot = (tid < 64) ? -sh[tid + 64] : sh[tid - 64];
    buf[tid] = __float2half_rn(y * c + rot * sn);
}

// ---------------- fp16 tensor-core flash attention (GQA-shared K/V) ----------------
// Block: 32 q-positions x 4 heads of one kv group = 128 A-rows; K-tiles of 64.
// 8 warps, each owns 16 A-rows. Q/K/V smem [row][d or kpos] stride 136 halves.
// V fragments via ldmatrix.trans (no transposed copy anywhere).
#define AST_H 136
#define PST_H 72
#define ATT_SMEM ((128*AST_H + 64*AST_H + 64*AST_H + 8*16*PST_H) * 2)

__global__ void __launch_bounds__(256) attn_f16_kernel() {
    extern __shared__ __half smh[];
    __half* Qs = smh;                        // [128][136]  rows = 4 heads x 32 q
    __half* Ks = Qs + 128 * AST_H;           // [64][136]   rows = kpos
    __half* Vs = Ks + 64 * AST_H;            // [64][136]   rows = kpos, cols = d
    __half* Pw = Vs + 64 * AST_H;            // 8 x [16][72]

    const int qt = 63 - blockIdx.x;          // large tiles first
    const int kvh = blockIdx.y, b = blockIdx.z;
    const int tid = threadIdx.x;
    const int warp = tid >> 5, lane = tid & 31;
    const int g = lane >> 2, tq = lane & 3;
    const float scale = 0.08838834764831845f;

    __half* Ps = Pw + warp * 16 * PST_H;
    const int rloc0 = warp * 16 + g;
    const int q0 = qt * 32 + (rloc0 & 31);
    const int head = kvh * 4 + (rloc0 >> 5);

    // fragment smem byte addresses
    const uint32_t qAddr = smem_u32(Qs) +
        (uint32_t)((warp * 16 + (lane & 15)) * AST_H) * 2 + ((lane & 16) ? 16u : 0u);
    const uint32_t kAddr = smem_u32(Ks) +
        (uint32_t)(((lane & 7) + ((lane & 16) >> 1)) * AST_H) * 2 + ((lane & 8) << 1);
    const uint32_t vAddr = smem_u32(Vs) +
        (uint32_t)(((lane & 7) + ((lane & 8) ? 8 : 0)) * AST_H) * 2 + ((lane & 16) ? 16u : 0u);
    const uint32_t pAddr = smem_u32(Ps) +
        (uint32_t)((lane & 15) * PST_H) * 2 + ((lane & 16) ? 16u : 0u);

    // load Q tile: row r -> head kvh*4 + r/32, qpos qt*32 + r%32; 128 halves = 16 chunks
#pragma unroll
    for (int i = 0; i < 8; i++) {
        int e = tid + (i << 8);
        int r = e >> 4, ds = (e & 15) << 3;
        cp16s(smem_u32(&Qs[r * AST_H + ds]),
              &g_qkv[(size_t)(b * SEQ + qt * 32 + (r & 31)) * QKVS +
                     (size_t)(kvh * 4 + (r >> 5)) * HD + ds]);
    }
    asm volatile("cp.async.commit_group;\n");

    float m0 = -1e30f, m1 = -1e30f, l0 = 0.f, l1 = 0.f;
    float o[16][4];
#pragma unroll
    for (int nt = 0; nt < 16; nt++)
#pragma unroll
        for (int e = 0; e < 4; e++) o[nt][e] = 0.f;

    const int nkt = (qt * 32 + 31) / 64 + 1;
    for (int kt = 0; kt < nkt; kt++) {
        if (kt) __syncthreads();
        const int kBase = kt * 64;
#pragma unroll
        for (int i = 0; i < 4; i++) {
            int e = tid + (i << 8);
            int r = e >> 4, ds = (e & 15) << 3;
            const size_t go = (size_t)(b * SEQ + kBase + r) * QKVS + (size_t)kvh * HD + ds;
            cp16s(smem_u32(&Ks[r * AST_H + ds]), &g_qkv[go + 4096]);
            cp16s(smem_u32(&Vs[r * AST_H + ds]), &g_qkv[go + 5120]);
        }
        asm volatile("cp.async.commit_group;\n");
        asm volatile("cp.async.wait_group 0;\n");
        __syncthreads();

        // ---- S = Q K^T : 16 rows x 64 kpos per warp; 8 k16 steps over d ----
        float s[8][4];
#pragma unroll
        for (int nt = 0; nt < 8; nt++)
#pragma unroll
            for (int e = 0; e < 4; e++) s[nt][e] = 0.f;

#pragma unroll
        for (int ks = 0; ks < 8; ks++) {
            unsigned qa[4];
            ldsm4(qa[0], qa[1], qa[2], qa[3], qAddr + (uint32_t)(ks * 32));
#pragma unroll
            for (int p = 0; p < 4; p++) {
                unsigned kb[4];
                ldsm4(kb[0], kb[1], kb[2], kb[3],
                      kAddr + (uint32_t)(p * 16 * AST_H * 2 + ks * 32));
                mma_f16(s[2*p][0], s[2*p][1], s[2*p][2], s[2*p][3],
                        qa[0], qa[1], qa[2], qa[3], kb[0], kb[1]);
                mma_f16(s[2*p+1][0], s[2*p+1][1], s[2*p+1][2], s[2*p+1][3],
                        qa[0], qa[1], qa[2], qa[3], kb[2], kb[3]);
            }
        }

        // ---- scale + causal mask ----
        const bool edge = (kBase + 63 > qt * 32);
#pragma unroll
        for (int nt = 0; nt < 8; nt++) {
            int c0 = kBase + nt * 8 + tq * 2;
            s[nt][0] *= scale; s[nt][1] *= scale;
            s[nt][2] *= scale; s[nt][3] *= scale;
            if (edge) {
                if (c0     > q0)     s[nt][0] = -1e30f;
                if (c0 + 1 > q0)     s[nt][1] = -1e30f;
                if (c0     > q0 + 8) s[nt][2] = -1e30f;
                if (c0 + 1 > q0 + 8) s[nt][3] = -1e30f;
            }
        }

        // ---- online softmax (rows q0, q0+8; quad reduction) ----
        float mx0 = -1e30f, mx1 = -1e30f;
#pragma unroll
        for (int nt = 0; nt < 8; nt++) {
            mx0 = fmaxf(mx0, fmaxf(s[nt][0], s[nt][1]));
            mx1 = fmaxf(mx1, fmaxf(s[nt][2], s[nt][3]));
        }
        mx0 = fmaxf(mx0, __shfl_xor_sync(0xffffffffu, mx0, 1));
        mx0 = fmaxf(mx0, __shfl_xor_sync(0xffffffffu, mx0, 2));
        mx1 = fmaxf(mx1, __shfl_xor_sync(0xffffffffu, mx1, 1));
        mx1 = fmaxf(mx1, __shfl_xor_sync(0xffffffffu, mx1, 2));

        float mn0 = fmaxf(m0, mx0), mn1 = fmaxf(m1, mx1);
        float al0 = __expf(m0 - mn0), al1 = __expf(m1 - mn1);
        m0 = mn0; m1 = mn1;

        float ps0 = 0.f, ps1 = 0.f;
#pragma unroll
        for (int nt = 0; nt < 8; nt++) {
            float p0 = __expf(s[nt][0] - mn0);
            float p1 = __expf(s[nt][1] - mn0);
            float p2 = __expf(s[nt][2] - mn1);
            float p3 = __expf(s[nt][3] - mn1);
            ps0 += p0 + p1; ps1 += p2 + p3;
            int c0 = nt * 8 + tq * 2;
            *(__half2*)&Ps[(g)     * PST_H + c0] = __floats2half2_rn(p0, p1);
            *(__half2*)&Ps[(g + 8) * PST_H + c0] = __floats2half2_rn(p2, p3);
        }
        ps0 += __shfl_xor_sync(0xffffffffu, ps0, 1);
        ps0 += __shfl_xor_sync(0xffffffffu, ps0, 2);
        ps1 += __shfl_xor_sync(0xffffffffu, ps1, 1);
        ps1 += __shfl_xor_sync(0xffffffffu, ps1, 2);
        l0 = l0 * al0 + ps0;
        l1 = l1 * al1 + ps1;

#pragma unroll
        for (int nt = 0; nt < 16; nt++) {
            o[nt][0] *= al0; o[nt][1] *= al0;
            o[nt][2] *= al1; o[nt][3] *= al1;
        }
        __syncwarp();

        // ---- O += P V : 16 rows x 128 d per warp; 4 k16 steps over kpos ----
#pragma unroll
        for (int ks = 0; ks < 4; ks++) {
            unsigned pa[4];
            ldsm4(pa[0], pa[1], pa[2], pa[3], pAddr + (uint32_t)(ks * 32));
            const uint32_t vRow = vAddr + (uint32_t)(ks * 16 * AST_H * 2);
#pragma unroll
            for (int p = 0; p < 8; p++) {
                unsigned vb[4];
                ldsm4t(vb[0], vb[1], vb[2], vb[3], vRow + (uint32_t)(p * 32));
                mma_f16(o[2*p][0], o[2*p][1], o[2*p][2], o[2*p][3],
                        pa[0], pa[1], pa[2], pa[3], vb[0], vb[1]);
                mma_f16(o[2*p+1][0], o[2*p+1][1], o[2*p+1][2], o[2*p+1][3],
                        pa[0], pa[1], pa[2], pa[3], vb[2], vb[3]);
            }
        }
    }

    // ---- epilogue (half output for final GEMM) ----
    float inv0 = 1.0f / l0, inv1 = 1.0f / l1;
    const size_t r0off = (size_t)(b * SEQ + q0) * QDIM + (size_t)head * HD;
    const size_t r1off = r0off + 8 * QDIM;
#pragma unroll
    for (int nt = 0; nt < 16; nt++) {
        int c0 = nt * 8 + tq * 2;
        *(__half2*)&g_ao[r0off + c0] = __floats2half2_rn(o[nt][0] * inv0, o[nt][1] * inv0);
        *(__half2*)&g_ao[r1off + c0] = __floats2half2_rn(o[nt][2] * inv1, o[nt][3] * inv1);
    }
}

// ---------------- launch ----------------
extern "C" void kernel_launch(void* const* d_in, const int* in_sizes, int n_in,
                              void* d_out, int out_size) {
    const float* hid = (const float*)d_in[0];
    const int*   pos = (const int*)d_in[1];
    const float* Wq  = (const float*)d_in[2];
    const float* Wk  = (const float*)d_in[3];
    const float* Wv  = (const float*)d_in[4];
    const float* Wo  = (const float*)d_in[5];
    const float* qw  = (const float*)d_in[6];
    const float* kw  = (const float*)d_in[7];
    float* out = (float*)d_out;

    __half *hid_h, *wtall, *wot, *qkv, *ao;
    cudaGetSymbolAddress((void**)&hid_h, g_hid_h);
    cudaGetSymbolAddress((void**)&wtall, g_WtAll);
    cudaGetSymbolAddress((void**)&wot, g_WoT);
    cudaGetSymbolAddress((void**)&qkv, g_qkv);
    cudaGetSymbolAddress((void**)&ao, g_ao);

    cudaFuncSetAttribute(gemm_f16_kernel<__half>, cudaFuncAttributeMaxDynamicSharedMemorySize, GEMM_SMEM);
    cudaFuncSetAttribute(gemm_f16_kernel<float>, cudaFuncAttributeMaxDynamicSharedMemorySize, GEMM_SMEM);
    cudaFuncSetAttribute(attn_f16_kernel, cudaFuncAttributeMaxDynamicSharedMemorySize, ATT_SMEM);

    // hidden -> fp16
    {
        int n4 = T_TOK * HIDN / 4;
        conv_half_kernel<<<(n4 + 255) / 256, 256>>>((const float4*)hid, (__half2*)hid_h, n4);
    }
    // transpose weights -> K-major fp16
    {
        dim3 blk(32, 8);
        transpose_half_kernel<<<dim3(QDIM / 32, HIDN / 32), blk>>>(Wq, wtall, HIDN, QDIM);
        transpose_half_kernel<<<dim3(KVDIM / 32, HIDN / 32), blk>>>(Wk, wtall + (size_t)4096 * HIDN, HIDN, KVDIM);
        transpose_half_kernel<<<dim3(KVDIM / 32, HIDN / 32), blk>>>(Wv, wtall + (size_t)5120 * HIDN, HIDN, KVDIM);
        transpose_half_kernel<<<dim3(HIDN / 32, QDIM / 32), blk>>>(Wo, wot, QDIM, HIDN);
    }
    rope_table_kernel<<<(T_TOK * 64) / 256, 256>>>(pos);

    // fused QKV projection: [4096,2560] @ [6144,2560]^T -> half [4096,6144]
    gemm_f16_kernel<__half><<<dim3(QKVS / TN, T_TOK / TM), 256, GEMM_SMEM>>>(
        hid_h, wtall, qkv, T_TOK, QKVS, HIDN);

    norm_rope_kernel<<<T_TOK * (NH + NKV), 128>>>(qw, kw);

    // attention (V transposed in-register via ldmatrix.trans)
    attn_f16_kernel<<<dim3(64, NKV, BATCH), 256, ATT_SMEM>>>();

    // output projection: [4096,4096] @ [2560,4096]^T -> fp32 out [4096,2560]
    gemm_f16_kernel<float><<<dim3(HIDN / TN, T_TOK / TM), 256, GEMM_SMEM>>>(
        ao, wot, out, T_TOK, HIDN, QDIM);
}